// round 5
// baseline (speedup 1.0000x reference)
#include <cuda_runtime.h>
#include <cstdint>

#define NN      100000
#define EE      3200000
#define IN_DIM  512
#define HID     256
#define OUTD    64

// ---------------- device scratch (static: allocated at module load) -----------
__device__ float  g_hidden[(size_t)NN * HID];   // 102.4 MB
__device__ float  g_h0[(size_t)NN * OUTD];      // 25.6 MB
__device__ float  g_hA[(size_t)NN * OUTD];      // 25.6 MB
__device__ float  g_hB[(size_t)NN * OUTD];      // 25.6 MB
__device__ int    g_cnt[NN];
__device__ int    g_rowptr[NN + 1];
__device__ int    g_cursor[NN];
__device__ float  g_dinv[NN];
__device__ float2 g_edge[EE];                   // {src_bits, norm} 25.6 MB
__device__ int    g_is64;                       // edge_index dtype flag

// ---------------- dtype detection ---------------------------------------------
// If the buffer is int64 (values < 2^31, little-endian), every odd int32 word
// is 0. If it is int32, odd words are uniform random node ids (P(zero)=1e-5).
__global__ void k_detect(const int* __restrict__ p32) {
    if (threadIdx.x == 0 && blockIdx.x == 0) {
        int all_zero = 1;
        for (int i = 0; i < 64; ++i)
            if (p32[2 * i + 1] != 0) { all_zero = 0; break; }
        g_is64 = all_zero;
    }
}

__device__ __forceinline__ int load_idx(const void* ei, size_t pos) {
    if (g_is64) return (int)((const long long*)ei)[pos];
    return ((const int*)ei)[pos];
}

// ---------------- preprocessing ------------------------------------------------
__global__ void k_zero(int n) {
    int i = blockIdx.x * blockDim.x + threadIdx.x;
    if (i < n) g_cnt[i] = 0;
}

__global__ void k_degree(const void* __restrict__ ei, int E) {
    int e = blockIdx.x * blockDim.x + threadIdx.x;
    if (e < E) {
        int d = load_idx(ei, (size_t)E + e);   // dst row
        atomicAdd(&g_cnt[d], 1);
    }
}

__global__ void k_dinv(int n) {
    int i = blockIdx.x * blockDim.x + threadIdx.x;
    if (i < n) {
        float deg = (float)(g_cnt[i] + 1);      // +1 self loop
        g_dinv[i] = rsqrtf(deg);
    }
}

// single-block exclusive scan of g_cnt -> g_rowptr / g_cursor
__global__ void k_scan(int n) {
    __shared__ int sp[1024];
    int t = threadIdx.x;
    int chunk = (n + 1023) >> 10;
    int lo = t * chunk;
    int hi = min(n, lo + chunk);
    int s = 0;
    for (int i = lo; i < hi; ++i) s += g_cnt[i];
    sp[t] = s;
    __syncthreads();
    for (int off = 1; off < 1024; off <<= 1) {
        int v = (t >= off) ? sp[t - off] : 0;
        __syncthreads();
        sp[t] += v;
        __syncthreads();
    }
    int run = sp[t] - s;   // exclusive prefix
    for (int i = lo; i < hi; ++i) {
        g_rowptr[i] = run;
        g_cursor[i] = run;
        run += g_cnt[i];
    }
    if (t == 1023) g_rowptr[n] = sp[1023];
}

__global__ void k_scatter(const void* __restrict__ ei, int E) {
    int e = blockIdx.x * blockDim.x + threadIdx.x;
    if (e < E) {
        int s = load_idx(ei, (size_t)e);
        int d = load_idx(ei, (size_t)E + e);
        int slot = atomicAdd(&g_cursor[d], 1);
        float nrm = g_dinv[s] * g_dinv[d];
        g_edge[slot] = make_float2(__int_as_float(s), nrm);
    }
}

// ---------------- GEMM1: hidden = relu(x @ W1 + b1)   [n,512]x[512,256] -------
__global__ __launch_bounds__(256, 2)
void k_gemm1(const float* __restrict__ X, const float* __restrict__ W,
             const float* __restrict__ bias, int n) {
    __shared__ __align__(16) float xs[32][68];    // transposed x tile [k][m]
    __shared__ __align__(16) float ws[32][256];   // W tile [k][c]
    int tid  = threadIdx.x;
    int row0 = blockIdx.x * 64;
    int ty   = tid >> 5;        // warp id 0..7 -> 8 rows each
    int tx   = tid & 31;        // 0..31       -> 8 cols each

    float acc[8][8];
#pragma unroll
    for (int i = 0; i < 8; ++i)
#pragma unroll
        for (int j = 0; j < 8; ++j) acc[i][j] = 0.f;

    for (int k0 = 0; k0 < IN_DIM; k0 += 32) {
        {
            int m  = tid >> 3;
            int kk = (tid & 7) * 4;
#pragma unroll
            for (int p = 0; p < 2; ++p) {
                int mm = m + p * 32;
                int gr = row0 + mm;
                float4 v = make_float4(0.f, 0.f, 0.f, 0.f);
                if (gr < n) v = *(const float4*)&X[(size_t)gr * IN_DIM + k0 + kk];
                xs[kk + 0][mm] = v.x;
                xs[kk + 1][mm] = v.y;
                xs[kk + 2][mm] = v.z;
                xs[kk + 3][mm] = v.w;
            }
        }
        {
            int kr = tid >> 6;            // 0..3
            int c4 = (tid & 63) * 4;      // 0..252
#pragma unroll
            for (int p = 0; p < 8; ++p) {
                int k = kr + p * 4;
                *(float4*)&ws[k][c4] = *(const float4*)&W[(size_t)(k0 + k) * HID + c4];
            }
        }
        __syncthreads();

#pragma unroll
        for (int k = 0; k < 32; ++k) {
            float4 a0 = *(const float4*)&xs[k][ty * 8];
            float4 a1 = *(const float4*)&xs[k][ty * 8 + 4];
            float4 b0 = *(const float4*)&ws[k][tx * 8];
            float4 b1 = *(const float4*)&ws[k][tx * 8 + 4];
            float a[8] = {a0.x, a0.y, a0.z, a0.w, a1.x, a1.y, a1.z, a1.w};
            float b[8] = {b0.x, b0.y, b0.z, b0.w, b1.x, b1.y, b1.z, b1.w};
#pragma unroll
            for (int i = 0; i < 8; ++i)
#pragma unroll
                for (int j = 0; j < 8; ++j)
                    acc[i][j] = fmaf(a[i], b[j], acc[i][j]);
        }
        __syncthreads();
    }

    int c = tx * 8;
    float4 bv0 = *(const float4*)&bias[c];
    float4 bv1 = *(const float4*)&bias[c + 4];
#pragma unroll
    for (int i = 0; i < 8; ++i) {
        int gr = row0 + ty * 8 + i;
        if (gr < n) {
            float4 o0, o1;
            o0.x = fmaxf(acc[i][0] + bv0.x, 0.f);
            o0.y = fmaxf(acc[i][1] + bv0.y, 0.f);
            o0.z = fmaxf(acc[i][2] + bv0.z, 0.f);
            o0.w = fmaxf(acc[i][3] + bv0.w, 0.f);
            o1.x = fmaxf(acc[i][4] + bv1.x, 0.f);
            o1.y = fmaxf(acc[i][5] + bv1.y, 0.f);
            o1.z = fmaxf(acc[i][6] + bv1.z, 0.f);
            o1.w = fmaxf(acc[i][7] + bv1.w, 0.f);
            *(float4*)&g_hidden[(size_t)gr * HID + c]     = o0;
            *(float4*)&g_hidden[(size_t)gr * HID + c + 4] = o1;
        }
    }
}

// ---------------- GEMM2: h0 = hidden @ W2 + b2   [n,256]x[256,64] -------------
__global__ __launch_bounds__(256, 2)
void k_gemm2(const float* __restrict__ W, const float* __restrict__ bias, int n) {
    __shared__ __align__(16) float hs[32][132];  // transposed hidden tile [k][m]
    __shared__ __align__(16) float ws[32][64];   // W2 tile [k][c]
    int tid  = threadIdx.x;
    int row0 = blockIdx.x * 128;
    int ty   = tid >> 4;   // 0..15 -> 8 rows
    int tx   = tid & 15;   // 0..15 -> 4 cols

    float acc[8][4];
#pragma unroll
    for (int i = 0; i < 8; ++i)
#pragma unroll
        for (int j = 0; j < 4; ++j) acc[i][j] = 0.f;

    for (int k0 = 0; k0 < HID; k0 += 32) {
        {
            int m  = tid >> 3;
            int kk = (tid & 7) * 4;
#pragma unroll
            for (int p = 0; p < 4; ++p) {
                int mm = m + p * 32;
                int gr = row0 + mm;
                float4 v = make_float4(0.f, 0.f, 0.f, 0.f);
                if (gr < n) v = *(const float4*)&g_hidden[(size_t)gr * HID + k0 + kk];
                hs[kk + 0][mm] = v.x;
                hs[kk + 1][mm] = v.y;
                hs[kk + 2][mm] = v.z;
                hs[kk + 3][mm] = v.w;
            }
        }
        {
            int kr = tid >> 4;            // 0..15
            int c4 = (tid & 15) * 4;      // 0..60
#pragma unroll
            for (int p = 0; p < 2; ++p) {
                int k = kr + p * 16;
                *(float4*)&ws[k][c4] = *(const float4*)&W[(size_t)(k0 + k) * OUTD + c4];
            }
        }
        __syncthreads();

#pragma unroll
        for (int k = 0; k < 32; ++k) {
            float4 a0 = *(const float4*)&hs[k][ty * 8];
            float4 a1 = *(const float4*)&hs[k][ty * 8 + 4];
            float4 b  = *(const float4*)&ws[k][tx * 4];
            float a[8] = {a0.x, a0.y, a0.z, a0.w, a1.x, a1.y, a1.z, a1.w};
            float bb[4] = {b.x, b.y, b.z, b.w};
#pragma unroll
            for (int i = 0; i < 8; ++i)
#pragma unroll
                for (int j = 0; j < 4; ++j)
                    acc[i][j] = fmaf(a[i], bb[j], acc[i][j]);
        }
        __syncthreads();
    }

    int c = tx * 4;
    float4 bv = *(const float4*)&bias[c];
#pragma unroll
    for (int i = 0; i < 8; ++i) {
        int gr = row0 + ty * 8 + i;
        if (gr < n) {
            float4 o;
            o.x = acc[i][0] + bv.x;
            o.y = acc[i][1] + bv.y;
            o.z = acc[i][2] + bv.z;
            o.w = acc[i][3] + bv.w;
            *(float4*)&g_h0[(size_t)gr * OUTD + c] = o;
        }
    }
}

// ---------------- propagation: one warp per dst node --------------------------
// h_out[d] = 0.9 * ( dinv[d]^2 * h_in[d] + sum_e norm_e * h_in[src_e] ) + 0.1 * h0[d]
// Buffer selection by integer id to stay free of cudaGetSymbolAddress:
//   sel: 0 = g_h0, 1 = g_hA, 2 = g_hB, 3 = dout (output only)
__global__ __launch_bounds__(256)
void k_prop(int in_sel, int out_sel, float* __restrict__ dout, int n) {
    int warp = (blockIdx.x * blockDim.x + threadIdx.x) >> 5;
    int lane = threadIdx.x & 31;
    if (warp >= n) return;
    int node = warp;

    const float* hin = (in_sel == 0) ? g_h0 : (in_sel == 1) ? g_hA : g_hB;
    float* hout = (out_sel == 1) ? g_hA : (out_sel == 2) ? g_hB : dout;

    const float2* __restrict__ hin2 = (const float2*)hin;

    int beg = g_rowptr[node];
    int end = g_rowptr[node + 1];
    float dv = g_dinv[node];

    float2 hv = hin2[(size_t)node * 32 + lane];
    float wself = dv * dv;
    float accx = wself * hv.x;
    float accy = wself * hv.y;

    for (int b = beg; b < end; b += 32) {
        int idx = b + lane;
        float2 ed = (idx < end) ? g_edge[idx] : make_float2(0.f, 0.f);
        int cnt = min(32, end - b);
#pragma unroll 4
        for (int j = 0; j < cnt; ++j) {
            int   s = __shfl_sync(0xffffffffu, __float_as_int(ed.x), j);
            float w = __shfl_sync(0xffffffffu, ed.y, j);
            float2 hs = hin2[(size_t)s * 32 + lane];
            accx = fmaf(w, hs.x, accx);
            accy = fmaf(w, hs.y, accy);
        }
    }

    float2 h0v = ((const float2*)g_h0)[(size_t)node * 32 + lane];
    float2 o;
    o.x = 0.9f * accx + 0.1f * h0v.x;
    o.y = 0.9f * accy + 0.1f * h0v.y;
    ((float2*)hout)[(size_t)node * 32 + lane] = o;
}

// ---------------- launcher -----------------------------------------------------
extern "C" void kernel_launch(void* const* d_in, const int* in_sizes, int n_in,
                              void* d_out, int out_size) {
    const float* x  = (const float*)d_in[0];
    const void*  ei = d_in[1];
    const float* W1 = (const float*)d_in[2];
    const float* b1 = (const float*)d_in[3];
    const float* W2 = (const float*)d_in[4];
    const float* b2 = (const float*)d_in[5];

    int n = in_sizes[0] / IN_DIM;
    int E = in_sizes[1] / 2;

    // dtype detection + CSR build
    k_detect <<<1, 32>>>((const int*)ei);
    k_zero   <<<(n + 255) / 256, 256>>>(n);
    k_degree <<<(E + 255) / 256, 256>>>(ei, E);
    k_dinv   <<<(n + 255) / 256, 256>>>(n);
    k_scan   <<<1, 1024>>>(n);
    k_scatter<<<(E + 255) / 256, 256>>>(ei, E);

    // MLP head
    k_gemm1<<<(n + 63) / 64, 256>>>(x, W1, b1, n);
    k_gemm2<<<(n + 127) / 128, 256>>>(W2, b2, n);

    // K = 10 propagation steps, ping-pong, final writes d_out
    int blocks = (n + 7) / 8;   // 8 warps / block
    int in_sel = 0;
    for (int i = 0; i < 10; ++i) {
        int out_sel = (i == 9) ? 3 : ((i & 1) ? 2 : 1);
        k_prop<<<blocks, 256>>>(in_sel, out_sel, (float*)d_out, n);
        in_sel = (i == 9) ? 3 : out_sel;
    }
}

// round 9
// speedup vs baseline: 1.2147x; 1.2147x over previous
#include <cuda_runtime.h>
#include <cuda_bf16.h>
#include <cstdint>

#define NN      100000
#define EE      3200000
#define IN_DIM  512
#define HID     256
#define OUTD    64

// ---------------- device scratch ------------------------------------------------
__device__ __nv_bfloat16 g_xhi[(size_t)NN * IN_DIM];
__device__ __nv_bfloat16 g_xlo[(size_t)NN * IN_DIM];
__device__ __nv_bfloat16 g_w1t_hi[(size_t)HID * IN_DIM];   // B^T: [256][512]
__device__ __nv_bfloat16 g_w1t_lo[(size_t)HID * IN_DIM];
__device__ __nv_bfloat16 g_w2t_hi[(size_t)OUTD * HID];     // B^T: [64][256]
__device__ __nv_bfloat16 g_w2t_lo[(size_t)OUTD * HID];
__device__ __nv_bfloat16 g_hid_hi[(size_t)NN * HID];
__device__ __nv_bfloat16 g_hid_lo[(size_t)NN * HID];
__device__ float  g_h0[(size_t)NN * OUTD];
__device__ float  g_hA[(size_t)NN * OUTD];
__device__ float  g_hB[(size_t)NN * OUTD];
__device__ int    g_cnt[NN];
__device__ int    g_rowptr[NN + 1];
__device__ int    g_cursor[NN];
__device__ float  g_dinv[NN];
__device__ float2 g_edge[EE];
__device__ int    g_is64;

// ---------------- helpers -------------------------------------------------------
__device__ __forceinline__ uint32_t smem_u32(const void* p) {
    uint32_t a;
    asm("{ .reg .u64 t; cvta.to.shared.u64 t, %1; cvt.u32.u64 %0, t; }" : "=r"(a) : "l"(p));
    return a;
}
__device__ __forceinline__ void cp16(uint32_t dst, const void* src) {
    asm volatile("cp.async.cg.shared.global [%0], [%1], 16;" :: "r"(dst), "l"(src) : "memory");
}
#define CP_COMMIT() asm volatile("cp.async.commit_group;" ::: "memory")
#define CP_WAIT(n)  asm volatile("cp.async.wait_group %0;" :: "n"(n) : "memory")

// mma.sync m16n8k16 bf16 -> f32, D += A*B
#define MMA(acc, A, B) \
    asm volatile("mma.sync.aligned.m16n8k16.row.col.f32.bf16.bf16.f32 " \
        "{%0,%1,%2,%3}, {%4,%5,%6,%7}, {%8,%9}, {%0,%1,%2,%3};" \
        : "+f"((acc)[0]), "+f"((acc)[1]), "+f"((acc)[2]), "+f"((acc)[3]) \
        : "r"((A)[0]), "r"((A)[1]), "r"((A)[2]), "r"((A)[3]), "r"((B)[0]), "r"((B)[1]))

#define A_STRIDE 144   // 128B row + 16B pad -> conflict-free frag LDS

// ---------------- dtype detection ------------------------------------------------
__global__ void k_detect(const int* __restrict__ p32) {
    if (threadIdx.x == 0 && blockIdx.x == 0) {
        int all_zero = 1;
        for (int i = 0; i < 64; ++i)
            if (p32[2 * i + 1] != 0) { all_zero = 0; break; }
        g_is64 = all_zero;
    }
}
__device__ __forceinline__ int load_idx(const void* ei, size_t pos) {
    if (g_is64) return (int)((const long long*)ei)[pos];
    return ((const int*)ei)[pos];
}

// ---------------- CSR build -------------------------------------------------------
__global__ void k_zero(int n) {
    int i = blockIdx.x * blockDim.x + threadIdx.x;
    if (i < n) g_cnt[i] = 0;
}
__global__ void k_degree(const void* __restrict__ ei, int E) {
    int e = blockIdx.x * blockDim.x + threadIdx.x;
    if (e < E) atomicAdd(&g_cnt[load_idx(ei, (size_t)E + e)], 1);
}
__global__ void k_dinv(int n) {
    int i = blockIdx.x * blockDim.x + threadIdx.x;
    if (i < n) g_dinv[i] = rsqrtf((float)(g_cnt[i] + 1));
}
__global__ void k_scan(int n) {
    __shared__ int sp[1024];
    int t = threadIdx.x;
    int chunk = (n + 1023) >> 10;
    int lo = t * chunk, hi = min(n, lo + chunk);
    int s = 0;
    for (int i = lo; i < hi; ++i) s += g_cnt[i];
    sp[t] = s;
    __syncthreads();
    for (int off = 1; off < 1024; off <<= 1) {
        int v = (t >= off) ? sp[t - off] : 0;
        __syncthreads();
        sp[t] += v;
        __syncthreads();
    }
    int run = sp[t] - s;
    for (int i = lo; i < hi; ++i) {
        g_rowptr[i] = run; g_cursor[i] = run; run += g_cnt[i];
    }
    if (t == 1023) g_rowptr[n] = sp[1023];
}
__global__ void k_scatter(const void* __restrict__ ei, int E) {
    int e = blockIdx.x * blockDim.x + threadIdx.x;
    if (e < E) {
        int s = load_idx(ei, (size_t)e);
        int d = load_idx(ei, (size_t)E + e);
        int slot = atomicAdd(&g_cursor[d], 1);
        g_edge[slot] = make_float2(__int_as_float(s), g_dinv[s] * g_dinv[d]);
    }
}

// ---------------- conversions -----------------------------------------------------
__global__ void k_convx(const float* __restrict__ X, int total4) {
    int i = blockIdx.x * blockDim.x + threadIdx.x;
    int stride = gridDim.x * blockDim.x;
    for (; i < total4; i += stride) {
        float4 v = ((const float4*)X)[i];
        __nv_bfloat16 h0 = __float2bfloat16(v.x), h1 = __float2bfloat16(v.y);
        __nv_bfloat16 h2 = __float2bfloat16(v.z), h3 = __float2bfloat16(v.w);
        __nv_bfloat162 a, b;
        a.x = h0; a.y = h1; b.x = h2; b.y = h3;
        ((__nv_bfloat162*)g_xhi)[2 * i]     = a;
        ((__nv_bfloat162*)g_xhi)[2 * i + 1] = b;
        __nv_bfloat162 c, d;
        c.x = __float2bfloat16(v.x - __bfloat162float(h0));
        c.y = __float2bfloat16(v.y - __bfloat162float(h1));
        d.x = __float2bfloat16(v.z - __bfloat162float(h2));
        d.y = __float2bfloat16(v.w - __bfloat162float(h3));
        ((__nv_bfloat162*)g_xlo)[2 * i]     = c;
        ((__nv_bfloat162*)g_xlo)[2 * i + 1] = d;
    }
}
__global__ void k_convw(const float* __restrict__ W1, const float* __restrict__ W2) {
    int i = blockIdx.x * blockDim.x + threadIdx.x;
    int stride = gridDim.x * blockDim.x;
    for (int e = i; e < IN_DIM * HID; e += stride) {
        int k = e >> 8, c = e & 255;
        float w = W1[e];
        __nv_bfloat16 h = __float2bfloat16(w);
        g_w1t_hi[(size_t)c * IN_DIM + k] = h;
        g_w1t_lo[(size_t)c * IN_DIM + k] = __float2bfloat16(w - __bfloat162float(h));
    }
    for (int e = i; e < HID * OUTD; e += stride) {
        int k = e >> 6, c = e & 63;
        float w = W2[e];
        __nv_bfloat16 h = __float2bfloat16(w);
        g_w2t_hi[(size_t)c * HID + k] = h;
        g_w2t_lo[(size_t)c * HID + k] = __float2bfloat16(w - __bfloat162float(h));
    }
}

// ================= GEMM1 (mma.sync): hidden = relu(x @ W1 + b1) ===================
// block tile 128x256, K=512 in 8 chunks of 64, double-buffered cp.async.
// buffer layout: Ah[128][144] | Al | Bh[256][144] | Bl
#define G1_AH 0
#define G1_AL 18432
#define G1_BH 36864
#define G1_BL 73728
#define G1_BUF 110592
#define G1_CHUNKS 8

__device__ __forceinline__ void g1_load(uint32_t sb, int row0, int n, int c) {
    int tid = threadIdx.x;
    int k0 = c * 64;
    uint32_t base = sb + (uint32_t)(c & 1) * G1_BUF;
#pragma unroll
    for (int p = 0; p < 4; ++p) {
        int id = tid + p * 256;
        int r = id >> 3, q = id & 7;
        int g = row0 + r; if (g >= n) g = n - 1;
        uint32_t off = (uint32_t)r * A_STRIDE + q * 16;
        cp16(base + G1_AH + off, g_xhi + (size_t)g * IN_DIM + k0 + q * 8);
        cp16(base + G1_AL + off, g_xlo + (size_t)g * IN_DIM + k0 + q * 8);
    }
#pragma unroll
    for (int p = 0; p < 8; ++p) {
        int id = tid + p * 256;
        int r = id >> 3, q = id & 7;
        uint32_t off = (uint32_t)r * A_STRIDE + q * 16;
        cp16(base + G1_BH + off, g_w1t_hi + (size_t)r * IN_DIM + k0 + q * 8);
        cp16(base + G1_BL + off, g_w1t_lo + (size_t)r * IN_DIM + k0 + q * 8);
    }
}

__global__ __launch_bounds__(256, 1)
void k_gemm1mma(const float* __restrict__ b1, int n) {
    extern __shared__ __align__(16) char smem[];
    uint32_t sb = smem_u32(smem);
    int tid = threadIdx.x, wid = tid >> 5, lane = tid & 31;
    int wm = wid & 1, wn = wid >> 1;          // 2 warps in M, 4 in N (warp tile 64x64)
    int g = lane >> 2, t = lane & 3;
    int row0 = blockIdx.x * 128;

    float acc[4][8][4];
#pragma unroll
    for (int i = 0; i < 4; ++i)
#pragma unroll
        for (int j = 0; j < 8; ++j)
#pragma unroll
            for (int v = 0; v < 4; ++v) acc[i][j][v] = 0.f;

    g1_load(sb, row0, n, 0);
    CP_COMMIT();

    for (int c = 0; c < G1_CHUNKS; ++c) {
        if (c + 1 < G1_CHUNKS) { g1_load(sb, row0, n, c + 1); CP_COMMIT(); CP_WAIT(1); }
        else CP_WAIT(0);
        __syncthreads();

        const char* buf = smem + (c & 1) * G1_BUF;
#pragma unroll
        for (int kt = 0; kt < 4; ++kt) {
            uint32_t ah[4][4], al[4][4];
#pragma unroll
            for (int mt = 0; mt < 4; ++mt) {
                uint32_t o0 = (uint32_t)(wm * 64 + mt * 16 + g) * A_STRIDE + kt * 32 + t * 4;
                uint32_t o1 = o0 + 8 * A_STRIDE;
                ah[mt][0] = *(const uint32_t*)(buf + G1_AH + o0);
                ah[mt][1] = *(const uint32_t*)(buf + G1_AH + o1);
                ah[mt][2] = *(const uint32_t*)(buf + G1_AH + o0 + 16);
                ah[mt][3] = *(const uint32_t*)(buf + G1_AH + o1 + 16);
                al[mt][0] = *(const uint32_t*)(buf + G1_AL + o0);
                al[mt][1] = *(const uint32_t*)(buf + G1_AL + o1);
                al[mt][2] = *(const uint32_t*)(buf + G1_AL + o0 + 16);
                al[mt][3] = *(const uint32_t*)(buf + G1_AL + o1 + 16);
            }
#pragma unroll
            for (int nh = 0; nh < 2; ++nh) {            // two halves of 4 n-tiles
                uint32_t bh[4][2], bl[4][2];
#pragma unroll
                for (int nq = 0; nq < 4; ++nq) {
                    int nt = nh * 4 + nq;
                    uint32_t o0 = (uint32_t)(wn * 64 + nt * 8 + g) * A_STRIDE + kt * 32 + t * 4;
                    bh[nq][0] = *(const uint32_t*)(buf + G1_BH + o0);
                    bh[nq][1] = *(const uint32_t*)(buf + G1_BH + o0 + 16);
                    bl[nq][0] = *(const uint32_t*)(buf + G1_BL + o0);
                    bl[nq][1] = *(const uint32_t*)(buf + G1_BL + o0 + 16);
                }
#pragma unroll
                for (int mt = 0; mt < 4; ++mt)
#pragma unroll
                    for (int nq = 0; nq < 4; ++nq) {
                        MMA(acc[mt][nh * 4 + nq], ah[mt], bh[nq]);
                        MMA(acc[mt][nh * 4 + nq], ah[mt], bl[nq]);
                        MMA(acc[mt][nh * 4 + nq], al[mt], bh[nq]);
                    }
            }
        }
        __syncthreads();
    }

    // epilogue: bias + relu, split to bf16 hi/lo
#pragma unroll
    for (int nt = 0; nt < 8; ++nt) {
        int col = wn * 64 + nt * 8 + 2 * t;
        float bv0 = b1[col], bv1 = b1[col + 1];
#pragma unroll
        for (int mt = 0; mt < 4; ++mt) {
            int r = row0 + wm * 64 + mt * 16 + g;
#pragma unroll
            for (int h = 0; h < 2; ++h) {
                int rr = r + h * 8;
                if (rr < n) {
                    float v0 = fmaxf(acc[mt][nt][2 * h]     + bv0, 0.f);
                    float v1 = fmaxf(acc[mt][nt][2 * h + 1] + bv1, 0.f);
                    __nv_bfloat16 h0 = __float2bfloat16(v0), h1 = __float2bfloat16(v1);
                    __nv_bfloat162 hp; hp.x = h0; hp.y = h1;
                    __nv_bfloat162 lp;
                    lp.x = __float2bfloat16(v0 - __bfloat162float(h0));
                    lp.y = __float2bfloat16(v1 - __bfloat162float(h1));
                    *(__nv_bfloat162*)(g_hid_hi + (size_t)rr * HID + col) = hp;
                    *(__nv_bfloat162*)(g_hid_lo + (size_t)rr * HID + col) = lp;
                }
            }
        }
    }
}

// ================= GEMM2 (mma.sync): h0 = hidden @ W2 + b2 ========================
// block tile 128x64, K=256 in 4 chunks of 64.
#define G2_AH 0
#define G2_AL 18432
#define G2_BH 36864
#define G2_BL 46080
#define G2_BUF 55296
#define G2_CHUNKS 4

__device__ __forceinline__ void g2_load(uint32_t sb, int row0, int n, int c) {
    int tid = threadIdx.x;
    int k0 = c * 64;
    uint32_t base = sb + (uint32_t)(c & 1) * G2_BUF;
#pragma unroll
    for (int p = 0; p < 4; ++p) {
        int id = tid + p * 256;
        int r = id >> 3, q = id & 7;
        int g = row0 + r; if (g >= n) g = n - 1;
        uint32_t off = (uint32_t)r * A_STRIDE + q * 16;
        cp16(base + G2_AH + off, g_hid_hi + (size_t)g * HID + k0 + q * 8);
        cp16(base + G2_AL + off, g_hid_lo + (size_t)g * HID + k0 + q * 8);
    }
#pragma unroll
    for (int p = 0; p < 2; ++p) {
        int id = tid + p * 256;
        int r = id >> 3, q = id & 7;
        uint32_t off = (uint32_t)r * A_STRIDE + q * 16;
        cp16(base + G2_BH + off, g_w2t_hi + (size_t)r * HID + k0 + q * 8);
        cp16(base + G2_BL + off, g_w2t_lo + (size_t)r * HID + k0 + q * 8);
    }
}

__global__ __launch_bounds__(256, 1)
void k_gemm2mma(const float* __restrict__ b2, int n) {
    extern __shared__ __align__(16) char smem[];
    uint32_t sb = smem_u32(smem);
    int tid = threadIdx.x, wid = tid >> 5, lane = tid & 31;
    int wm = wid & 1, wn = wid >> 1;          // warp tile 64x16
    int g = lane >> 2, t = lane & 3;
    int row0 = blockIdx.x * 128;

    float acc[4][2][4];
#pragma unroll
    for (int i = 0; i < 4; ++i)
#pragma unroll
        for (int j = 0; j < 2; ++j)
#pragma unroll
            for (int v = 0; v < 4; ++v) acc[i][j][v] = 0.f;

    g2_load(sb, row0, n, 0);
    CP_COMMIT();

    for (int c = 0; c < G2_CHUNKS; ++c) {
        if (c + 1 < G2_CHUNKS) { g2_load(sb, row0, n, c + 1); CP_COMMIT(); CP_WAIT(1); }
        else CP_WAIT(0);
        __syncthreads();

        const char* buf = smem + (c & 1) * G2_BUF;
#pragma unroll
        for (int kt = 0; kt < 4; ++kt) {
            uint32_t ah[4][4], al[4][4], bh[2][2], bl[2][2];
#pragma unroll
            for (int mt = 0; mt < 4; ++mt) {
                uint32_t o0 = (uint32_t)(wm * 64 + mt * 16 + g) * A_STRIDE + kt * 32 + t * 4;
                uint32_t o1 = o0 + 8 * A_STRIDE;
                ah[mt][0] = *(const uint32_t*)(buf + G2_AH + o0);
                ah[mt][1] = *(const uint32_t*)(buf + G2_AH + o1);
                ah[mt][2] = *(const uint32_t*)(buf + G2_AH + o0 + 16);
                ah[mt][3] = *(const uint32_t*)(buf + G2_AH + o1 + 16);
                al[mt][0] = *(const uint32_t*)(buf + G2_AL + o0);
                al[mt][1] = *(const uint32_t*)(buf + G2_AL + o1);
                al[mt][2] = *(const uint32_t*)(buf + G2_AL + o0 + 16);
                al[mt][3] = *(const uint32_t*)(buf + G2_AL + o1 + 16);
            }
#pragma unroll
            for (int nt = 0; nt < 2; ++nt) {
                uint32_t o0 = (uint32_t)(wn * 16 + nt * 8 + g) * A_STRIDE + kt * 32 + t * 4;
                bh[nt][0] = *(const uint32_t*)(buf + G2_BH + o0);
                bh[nt][1] = *(const uint32_t*)(buf + G2_BH + o0 + 16);
                bl[nt][0] = *(const uint32_t*)(buf + G2_BL + o0);
                bl[nt][1] = *(const uint32_t*)(buf + G2_BL + o0 + 16);
            }
#pragma unroll
            for (int mt = 0; mt < 4; ++mt)
#pragma unroll
                for (int nt = 0; nt < 2; ++nt) {
                    MMA(acc[mt][nt], ah[mt], bh[nt]);
                    MMA(acc[mt][nt], ah[mt], bl[nt]);
                    MMA(acc[mt][nt], al[mt], bh[nt]);
                }
        }
        __syncthreads();
    }

#pragma unroll
    for (int nt = 0; nt < 2; ++nt) {
        int col = wn * 16 + nt * 8 + 2 * t;
        float bv0 = b2[col], bv1 = b2[col + 1];
#pragma unroll
        for (int mt = 0; mt < 4; ++mt) {
            int r = row0 + wm * 64 + mt * 16 + g;
#pragma unroll
            for (int h = 0; h < 2; ++h) {
                int rr = r + h * 8;
                if (rr < n) {
                    float2 o;
                    o.x = acc[mt][nt][2 * h]     + bv0;
                    o.y = acc[mt][nt][2 * h + 1] + bv1;
                    *(float2*)(g_h0 + (size_t)rr * OUTD + col) = o;
                }
            }
        }
    }
}

// ---------------- propagation: one warp per dst node ------------------------------
__global__ __launch_bounds__(256)
void k_prop(int in_sel, int out_sel, float* __restrict__ dout, int n) {
    int warp = (blockIdx.x * blockDim.x + threadIdx.x) >> 5;
    int lane = threadIdx.x & 31;
    if (warp >= n) return;
    int node = warp;

    const float* hin = (in_sel == 0) ? g_h0 : (in_sel == 1) ? g_hA : g_hB;
    float* hout = (out_sel == 1) ? g_hA : (out_sel == 2) ? g_hB : dout;

    const float2* __restrict__ hin2 = (const float2*)hin;

    int beg = g_rowptr[node];
    int end = g_rowptr[node + 1];
    float dv = g_dinv[node];

    float2 hv = hin2[(size_t)node * 32 + lane];
    float wself = dv * dv;
    float accx = wself * hv.x;
    float accy = wself * hv.y;

    for (int b = beg; b < end; b += 32) {
        int idx = b + lane;
        float2 ed = (idx < end) ? g_edge[idx] : make_float2(0.f, 0.f);
        int cnt = min(32, end - b);
#pragma unroll 4
        for (int j = 0; j < cnt; ++j) {
            int   s = __shfl_sync(0xffffffffu, __float_as_int(ed.x), j);
            float w = __shfl_sync(0xffffffffu, ed.y, j);
            float2 hs = hin2[(size_t)s * 32 + lane];
            accx = fmaf(w, hs.x, accx);
            accy = fmaf(w, hs.y, accy);
        }
    }

    float2 h0v = ((const float2*)g_h0)[(size_t)node * 32 + lane];
    float2 o;
    o.x = 0.9f * accx + 0.1f * h0v.x;
    o.y = 0.9f * accy + 0.1f * h0v.y;
    ((float2*)hout)[(size_t)node * 32 + lane] = o;
}

// ---------------- launcher --------------------------------------------------------
extern "C" void kernel_launch(void* const* d_in, const int* in_sizes, int n_in,
                              void* d_out, int out_size) {
    const float* x  = (const float*)d_in[0];
    const void*  ei = d_in[1];
    const float* W1 = (const float*)d_in[2];
    const float* b1 = (const float*)d_in[3];
    const float* W2 = (const float*)d_in[4];
    const float* b2 = (const float*)d_in[5];

    int n = in_sizes[0] / IN_DIM;
    int E = in_sizes[1] / 2;

    cudaFuncSetAttribute(k_gemm1mma, cudaFuncAttributeMaxDynamicSharedMemorySize, 2 * G1_BUF);
    cudaFuncSetAttribute(k_gemm2mma, cudaFuncAttributeMaxDynamicSharedMemorySize, 2 * G2_BUF);

    // dtype detection + CSR build
    k_detect <<<1, 32>>>((const int*)ei);
    k_zero   <<<(n + 255) / 256, 256>>>(n);
    k_degree <<<(E + 255) / 256, 256>>>(ei, E);
    k_dinv   <<<(n + 255) / 256, 256>>>(n);
    k_scan   <<<1, 1024>>>(n);
    k_scatter<<<(E + 255) / 256, 256>>>(ei, E);

    // conversions
    k_convw<<<128, 256>>>(W1, W2);
    k_convx<<<2048, 256>>>(x, n * IN_DIM / 4);

    // MLP head on tensor cores (legacy mma.sync path)
    int mtiles = (n + 127) / 128;
    k_gemm1mma<<<mtiles, 256, 2 * G1_BUF>>>(b1, n);
    k_gemm2mma<<<mtiles, 256, 2 * G2_BUF>>>(b2, n);

    // K = 10 propagation steps, ping-pong, final writes d_out
    int blocks = (n + 7) / 8;
    int in_sel = 0;
    for (int i = 0; i < 10; ++i) {
        int out_sel = (i == 9) ? 3 : ((i & 1) ? 2 : 1);
        k_prop<<<blocks, 256>>>(in_sel, out_sel, (float*)d_out, n);
        in_sel = out_sel;
    }
}

// round 10
// speedup vs baseline: 1.2521x; 1.0308x over previous
#include <cuda_runtime.h>
#include <cuda_bf16.h>
#include <cuda_fp16.h>
#include <cstdint>

#define NN      100000
#define EE      3200000
#define IN_DIM  512
#define HID     256
#define OUTD    64

// ---------------- device scratch ------------------------------------------------
__device__ __nv_bfloat16 g_xhi[(size_t)NN * IN_DIM];
__device__ __nv_bfloat16 g_xlo[(size_t)NN * IN_DIM];
__device__ __nv_bfloat16 g_w1t_hi[(size_t)HID * IN_DIM];   // B^T: [256][512]
__device__ __nv_bfloat16 g_w1t_lo[(size_t)HID * IN_DIM];
__device__ __nv_bfloat16 g_w2t_hi[(size_t)OUTD * HID];     // B^T: [64][256]
__device__ __nv_bfloat16 g_w2t_lo[(size_t)OUTD * HID];
__device__ __nv_bfloat16 g_hid_hi[(size_t)NN * HID];
__device__ __nv_bfloat16 g_hid_lo[(size_t)NN * HID];
__device__ float  g_h0[(size_t)NN * OUTD];                 // fp32 teleport term
__device__ __half g_f0[(size_t)NN * OUTD];                 // fp16 h0 (iter-0 input)
__device__ __half g_fA[(size_t)NN * OUTD];                 // fp16 ping
__device__ __half g_fB[(size_t)NN * OUTD];                 // fp16 pong
__device__ int    g_cnt[NN];
__device__ int    g_rowptr[NN + 1];
__device__ int    g_cursor[NN];
__device__ float  g_dinv[NN];
__device__ float2 g_edge[EE];
__device__ int    g_is64;

// ---------------- helpers -------------------------------------------------------
__device__ __forceinline__ uint32_t smem_u32(const void* p) {
    uint32_t a;
    asm("{ .reg .u64 t; cvta.to.shared.u64 t, %1; cvt.u32.u64 %0, t; }" : "=r"(a) : "l"(p));
    return a;
}
__device__ __forceinline__ void cp16(uint32_t dst, const void* src) {
    asm volatile("cp.async.cg.shared.global [%0], [%1], 16;" :: "r"(dst), "l"(src) : "memory");
}
#define CP_COMMIT() asm volatile("cp.async.commit_group;" ::: "memory")
#define CP_WAIT(n)  asm volatile("cp.async.wait_group %0;" :: "n"(n) : "memory")

// mma.sync m16n8k16 bf16 -> f32, D += A*B
#define MMA(acc, A, B) \
    asm volatile("mma.sync.aligned.m16n8k16.row.col.f32.bf16.bf16.f32 " \
        "{%0,%1,%2,%3}, {%4,%5,%6,%7}, {%8,%9}, {%0,%1,%2,%3};" \
        : "+f"((acc)[0]), "+f"((acc)[1]), "+f"((acc)[2]), "+f"((acc)[3]) \
        : "r"((A)[0]), "r"((A)[1]), "r"((A)[2]), "r"((A)[3]), "r"((B)[0]), "r"((B)[1]))

#define A_STRIDE 144   // 128B row + 16B pad -> conflict-free frag LDS

// ---------------- dtype detection ------------------------------------------------
__global__ void k_detect(const int* __restrict__ p32) {
    if (threadIdx.x == 0 && blockIdx.x == 0) {
        int all_zero = 1;
        for (int i = 0; i < 64; ++i)
            if (p32[2 * i + 1] != 0) { all_zero = 0; break; }
        g_is64 = all_zero;
    }
}
__device__ __forceinline__ int load_idx(const void* ei, size_t pos) {
    if (g_is64) return (int)((const long long*)ei)[pos];
    return ((const int*)ei)[pos];
}

// ---------------- CSR build -------------------------------------------------------
__global__ void k_zero(int n) {
    int i = blockIdx.x * blockDim.x + threadIdx.x;
    if (i < n) g_cnt[i] = 0;
}
__global__ void k_degree(const void* __restrict__ ei, int E) {
    int e = blockIdx.x * blockDim.x + threadIdx.x;
    if (e < E) atomicAdd(&g_cnt[load_idx(ei, (size_t)E + e)], 1);
}
__global__ void k_dinv(int n) {
    int i = blockIdx.x * blockDim.x + threadIdx.x;
    if (i < n) g_dinv[i] = rsqrtf((float)(g_cnt[i] + 1));
}
__global__ void k_scan(int n) {
    __shared__ int sp[1024];
    int t = threadIdx.x;
    int chunk = (n + 1023) >> 10;
    int lo = t * chunk, hi = min(n, lo + chunk);
    int s = 0;
    for (int i = lo; i < hi; ++i) s += g_cnt[i];
    sp[t] = s;
    __syncthreads();
    for (int off = 1; off < 1024; off <<= 1) {
        int v = (t >= off) ? sp[t - off] : 0;
        __syncthreads();
        sp[t] += v;
        __syncthreads();
    }
    int run = sp[t] - s;
    for (int i = lo; i < hi; ++i) {
        g_rowptr[i] = run; g_cursor[i] = run; run += g_cnt[i];
    }
    if (t == 1023) g_rowptr[n] = sp[1023];
}
__global__ void k_scatter(const void* __restrict__ ei, int E) {
    int e = blockIdx.x * blockDim.x + threadIdx.x;
    if (e < E) {
        int s = load_idx(ei, (size_t)e);
        int d = load_idx(ei, (size_t)E + e);
        int slot = atomicAdd(&g_cursor[d], 1);
        g_edge[slot] = make_float2(__int_as_float(s), g_dinv[s] * g_dinv[d]);
    }
}

// ---------------- conversions -----------------------------------------------------
__global__ void k_convx(const float* __restrict__ X, int total4) {
    int i = blockIdx.x * blockDim.x + threadIdx.x;
    int stride = gridDim.x * blockDim.x;
    for (; i < total4; i += stride) {
        float4 v = ((const float4*)X)[i];
        __nv_bfloat16 h0 = __float2bfloat16(v.x), h1 = __float2bfloat16(v.y);
        __nv_bfloat16 h2 = __float2bfloat16(v.z), h3 = __float2bfloat16(v.w);
        __nv_bfloat162 a, b;
        a.x = h0; a.y = h1; b.x = h2; b.y = h3;
        ((__nv_bfloat162*)g_xhi)[2 * i]     = a;
        ((__nv_bfloat162*)g_xhi)[2 * i + 1] = b;
        __nv_bfloat162 c, d;
        c.x = __float2bfloat16(v.x - __bfloat162float(h0));
        c.y = __float2bfloat16(v.y - __bfloat162float(h1));
        d.x = __float2bfloat16(v.z - __bfloat162float(h2));
        d.y = __float2bfloat16(v.w - __bfloat162float(h3));
        ((__nv_bfloat162*)g_xlo)[2 * i]     = c;
        ((__nv_bfloat162*)g_xlo)[2 * i + 1] = d;
    }
}
__global__ void k_convw(const float* __restrict__ W1, const float* __restrict__ W2) {
    int i = blockIdx.x * blockDim.x + threadIdx.x;
    int stride = gridDim.x * blockDim.x;
    for (int e = i; e < IN_DIM * HID; e += stride) {
        int k = e >> 8, c = e & 255;
        float w = W1[e];
        __nv_bfloat16 h = __float2bfloat16(w);
        g_w1t_hi[(size_t)c * IN_DIM + k] = h;
        g_w1t_lo[(size_t)c * IN_DIM + k] = __float2bfloat16(w - __bfloat162float(h));
    }
    for (int e = i; e < HID * OUTD; e += stride) {
        int k = e >> 6, c = e & 63;
        float w = W2[e];
        __nv_bfloat16 h = __float2bfloat16(w);
        g_w2t_hi[(size_t)c * HID + k] = h;
        g_w2t_lo[(size_t)c * HID + k] = __float2bfloat16(w - __bfloat162float(h));
    }
}

// ================= GEMM1 (mma.sync): hidden = relu(x @ W1 + b1) ===================
// block tile 128x256, K=512 in 8 chunks of 64, double-buffered cp.async.
#define G1_AH 0
#define G1_AL 18432
#define G1_BH 36864
#define G1_BL 73728
#define G1_BUF 110592
#define G1_CHUNKS 8

__device__ __forceinline__ void g1_load(uint32_t sb, int row0, int n, int c) {
    int tid = threadIdx.x;
    int k0 = c * 64;
    uint32_t base = sb + (uint32_t)(c & 1) * G1_BUF;
#pragma unroll
    for (int p = 0; p < 4; ++p) {
        int id = tid + p * 256;
        int r = id >> 3, q = id & 7;
        int g = row0 + r; if (g >= n) g = n - 1;
        uint32_t off = (uint32_t)r * A_STRIDE + q * 16;
        cp16(base + G1_AH + off, g_xhi + (size_t)g * IN_DIM + k0 + q * 8);
        cp16(base + G1_AL + off, g_xlo + (size_t)g * IN_DIM + k0 + q * 8);
    }
#pragma unroll
    for (int p = 0; p < 8; ++p) {
        int id = tid + p * 256;
        int r = id >> 3, q = id & 7;
        uint32_t off = (uint32_t)r * A_STRIDE + q * 16;
        cp16(base + G1_BH + off, g_w1t_hi + (size_t)r * IN_DIM + k0 + q * 8);
        cp16(base + G1_BL + off, g_w1t_lo + (size_t)r * IN_DIM + k0 + q * 8);
    }
}

__global__ __launch_bounds__(256, 1)
void k_gemm1mma(const float* __restrict__ b1, int n) {
    extern __shared__ __align__(16) char smem[];
    uint32_t sb = smem_u32(smem);
    int tid = threadIdx.x, wid = tid >> 5, lane = tid & 31;
    int wm = wid & 1, wn = wid >> 1;
    int g = lane >> 2, t = lane & 3;
    int row0 = blockIdx.x * 128;

    float acc[4][8][4];
#pragma unroll
    for (int i = 0; i < 4; ++i)
#pragma unroll
        for (int j = 0; j < 8; ++j)
#pragma unroll
            for (int v = 0; v < 4; ++v) acc[i][j][v] = 0.f;

    g1_load(sb, row0, n, 0);
    CP_COMMIT();

    for (int c = 0; c < G1_CHUNKS; ++c) {
        if (c + 1 < G1_CHUNKS) { g1_load(sb, row0, n, c + 1); CP_COMMIT(); CP_WAIT(1); }
        else CP_WAIT(0);
        __syncthreads();

        const char* buf = smem + (c & 1) * G1_BUF;
#pragma unroll
        for (int kt = 0; kt < 4; ++kt) {
            uint32_t ah[4][4], al[4][4];
#pragma unroll
            for (int mt = 0; mt < 4; ++mt) {
                uint32_t o0 = (uint32_t)(wm * 64 + mt * 16 + g) * A_STRIDE + kt * 32 + t * 4;
                uint32_t o1 = o0 + 8 * A_STRIDE;
                ah[mt][0] = *(const uint32_t*)(buf + G1_AH + o0);
                ah[mt][1] = *(const uint32_t*)(buf + G1_AH + o1);
                ah[mt][2] = *(const uint32_t*)(buf + G1_AH + o0 + 16);
                ah[mt][3] = *(const uint32_t*)(buf + G1_AH + o1 + 16);
                al[mt][0] = *(const uint32_t*)(buf + G1_AL + o0);
                al[mt][1] = *(const uint32_t*)(buf + G1_AL + o1);
                al[mt][2] = *(const uint32_t*)(buf + G1_AL + o0 + 16);
                al[mt][3] = *(const uint32_t*)(buf + G1_AL + o1 + 16);
            }
#pragma unroll
            for (int nh = 0; nh < 2; ++nh) {
                uint32_t bh[4][2], bl[4][2];
#pragma unroll
                for (int nq = 0; nq < 4; ++nq) {
                    int nt = nh * 4 + nq;
                    uint32_t o0 = (uint32_t)(wn * 64 + nt * 8 + g) * A_STRIDE + kt * 32 + t * 4;
                    bh[nq][0] = *(const uint32_t*)(buf + G1_BH + o0);
                    bh[nq][1] = *(const uint32_t*)(buf + G1_BH + o0 + 16);
                    bl[nq][0] = *(const uint32_t*)(buf + G1_BL + o0);
                    bl[nq][1] = *(const uint32_t*)(buf + G1_BL + o0 + 16);
                }
#pragma unroll
                for (int mt = 0; mt < 4; ++mt)
#pragma unroll
                    for (int nq = 0; nq < 4; ++nq) {
                        MMA(acc[mt][nh * 4 + nq], ah[mt], bh[nq]);
                        MMA(acc[mt][nh * 4 + nq], ah[mt], bl[nq]);
                        MMA(acc[mt][nh * 4 + nq], al[mt], bh[nq]);
                    }
            }
        }
        __syncthreads();
    }

#pragma unroll
    for (int nt = 0; nt < 8; ++nt) {
        int col = wn * 64 + nt * 8 + 2 * t;
        float bv0 = b1[col], bv1 = b1[col + 1];
#pragma unroll
        for (int mt = 0; mt < 4; ++mt) {
            int r = row0 + wm * 64 + mt * 16 + g;
#pragma unroll
            for (int h = 0; h < 2; ++h) {
                int rr = r + h * 8;
                if (rr < n) {
                    float v0 = fmaxf(acc[mt][nt][2 * h]     + bv0, 0.f);
                    float v1 = fmaxf(acc[mt][nt][2 * h + 1] + bv1, 0.f);
                    __nv_bfloat16 h0 = __float2bfloat16(v0), h1 = __float2bfloat16(v1);
                    __nv_bfloat162 hp; hp.x = h0; hp.y = h1;
                    __nv_bfloat162 lp;
                    lp.x = __float2bfloat16(v0 - __bfloat162float(h0));
                    lp.y = __float2bfloat16(v1 - __bfloat162float(h1));
                    *(__nv_bfloat162*)(g_hid_hi + (size_t)rr * HID + col) = hp;
                    *(__nv_bfloat162*)(g_hid_lo + (size_t)rr * HID + col) = lp;
                }
            }
        }
    }
}

// ================= GEMM2 (mma.sync): h0 = hidden @ W2 + b2 ========================
#define G2_AH 0
#define G2_AL 18432
#define G2_BH 36864
#define G2_BL 46080
#define G2_BUF 55296
#define G2_CHUNKS 4

__device__ __forceinline__ void g2_load(uint32_t sb, int row0, int n, int c) {
    int tid = threadIdx.x;
    int k0 = c * 64;
    uint32_t base = sb + (uint32_t)(c & 1) * G2_BUF;
#pragma unroll
    for (int p = 0; p < 4; ++p) {
        int id = tid + p * 256;
        int r = id >> 3, q = id & 7;
        int g = row0 + r; if (g >= n) g = n - 1;
        uint32_t off = (uint32_t)r * A_STRIDE + q * 16;
        cp16(base + G2_AH + off, g_hid_hi + (size_t)g * HID + k0 + q * 8);
        cp16(base + G2_AL + off, g_hid_lo + (size_t)g * HID + k0 + q * 8);
    }
#pragma unroll
    for (int p = 0; p < 2; ++p) {
        int id = tid + p * 256;
        int r = id >> 3, q = id & 7;
        uint32_t off = (uint32_t)r * A_STRIDE + q * 16;
        cp16(base + G2_BH + off, g_w2t_hi + (size_t)r * HID + k0 + q * 8);
        cp16(base + G2_BL + off, g_w2t_lo + (size_t)r * HID + k0 + q * 8);
    }
}

__global__ __launch_bounds__(256, 1)
void k_gemm2mma(const float* __restrict__ b2, int n) {
    extern __shared__ __align__(16) char smem[];
    uint32_t sb = smem_u32(smem);
    int tid = threadIdx.x, wid = tid >> 5, lane = tid & 31;
    int wm = wid & 1, wn = wid >> 1;
    int g = lane >> 2, t = lane & 3;
    int row0 = blockIdx.x * 128;

    float acc[4][2][4];
#pragma unroll
    for (int i = 0; i < 4; ++i)
#pragma unroll
        for (int j = 0; j < 2; ++j)
#pragma unroll
            for (int v = 0; v < 4; ++v) acc[i][j][v] = 0.f;

    g2_load(sb, row0, n, 0);
    CP_COMMIT();

    for (int c = 0; c < G2_CHUNKS; ++c) {
        if (c + 1 < G2_CHUNKS) { g2_load(sb, row0, n, c + 1); CP_COMMIT(); CP_WAIT(1); }
        else CP_WAIT(0);
        __syncthreads();

        const char* buf = smem + (c & 1) * G2_BUF;
#pragma unroll
        for (int kt = 0; kt < 4; ++kt) {
            uint32_t ah[4][4], al[4][4], bh[2][2], bl[2][2];
#pragma unroll
            for (int mt = 0; mt < 4; ++mt) {
                uint32_t o0 = (uint32_t)(wm * 64 + mt * 16 + g) * A_STRIDE + kt * 32 + t * 4;
                uint32_t o1 = o0 + 8 * A_STRIDE;
                ah[mt][0] = *(const uint32_t*)(buf + G2_AH + o0);
                ah[mt][1] = *(const uint32_t*)(buf + G2_AH + o1);
                ah[mt][2] = *(const uint32_t*)(buf + G2_AH + o0 + 16);
                ah[mt][3] = *(const uint32_t*)(buf + G2_AH + o1 + 16);
                al[mt][0] = *(const uint32_t*)(buf + G2_AL + o0);
                al[mt][1] = *(const uint32_t*)(buf + G2_AL + o1);
                al[mt][2] = *(const uint32_t*)(buf + G2_AL + o0 + 16);
                al[mt][3] = *(const uint32_t*)(buf + G2_AL + o1 + 16);
            }
#pragma unroll
            for (int nt = 0; nt < 2; ++nt) {
                uint32_t o0 = (uint32_t)(wn * 16 + nt * 8 + g) * A_STRIDE + kt * 32 + t * 4;
                bh[nt][0] = *(const uint32_t*)(buf + G2_BH + o0);
                bh[nt][1] = *(const uint32_t*)(buf + G2_BH + o0 + 16);
                bl[nt][0] = *(const uint32_t*)(buf + G2_BL + o0);
                bl[nt][1] = *(const uint32_t*)(buf + G2_BL + o0 + 16);
            }
#pragma unroll
            for (int mt = 0; mt < 4; ++mt)
#pragma unroll
                for (int nt = 0; nt < 2; ++nt) {
                    MMA(acc[mt][nt], ah[mt], bh[nt]);
                    MMA(acc[mt][nt], ah[mt], bl[nt]);
                    MMA(acc[mt][nt], al[mt], bh[nt]);
                }
        }
        __syncthreads();
    }

#pragma unroll
    for (int nt = 0; nt < 2; ++nt) {
        int col = wn * 16 + nt * 8 + 2 * t;
        float bv0 = b2[col], bv1 = b2[col + 1];
#pragma unroll
        for (int mt = 0; mt < 4; ++mt) {
            int r = row0 + wm * 64 + mt * 16 + g;
#pragma unroll
            for (int h = 0; h < 2; ++h) {
                int rr = r + h * 8;
                if (rr < n) {
                    float2 o;
                    o.x = acc[mt][nt][2 * h]     + bv0;
                    o.y = acc[mt][nt][2 * h + 1] + bv1;
                    *(float2*)(g_h0 + (size_t)rr * OUTD + col) = o;
                    *(__half2*)(g_f0 + (size_t)rr * OUTD + col) = __floats2half2_rn(o.x, o.y);
                }
            }
        }
    }
}

// ---------------- propagation: one warp per dst node, fp16 features ---------------
// h_out[d] = 0.9 * ( dinv[d]^2 * h_in[d] + sum_e norm_e * h_in[src_e] ) + 0.1 * h0[d]
// in_sel: 0 = g_f0, 1 = g_fA, 2 = g_fB   (all fp16)
// out_sel: 1 = g_fA, 2 = g_fB (fp16), 3 = dout (fp32 final)
__global__ __launch_bounds__(256)
void k_prop(int in_sel, int out_sel, float* __restrict__ dout, int n) {
    int warp = (blockIdx.x * blockDim.x + threadIdx.x) >> 5;
    int lane = threadIdx.x & 31;
    if (warp >= n) return;
    int node = warp;

    const __half2* __restrict__ hin = (const __half2*)
        ((in_sel == 0) ? g_f0 : (in_sel == 1) ? g_fA : g_fB);

    int beg = g_rowptr[node];
    int end = g_rowptr[node + 1];
    float dv = g_dinv[node];

    float2 hv = __half22float2(hin[(size_t)node * 32 + lane]);
    float wself = dv * dv;
    float accx = wself * hv.x;
    float accy = wself * hv.y;

    for (int b = beg; b < end; b += 32) {
        int idx = b + lane;
        float2 ed = (idx < end) ? g_edge[idx] : make_float2(0.f, 0.f);
        int cnt = min(32, end - b);
#pragma unroll 4
        for (int j = 0; j < cnt; ++j) {
            int   s = __shfl_sync(0xffffffffu, __float_as_int(ed.x), j);
            float w = __shfl_sync(0xffffffffu, ed.y, j);
            float2 hs = __half22float2(hin[(size_t)s * 32 + lane]);
            accx = fmaf(w, hs.x, accx);
            accy = fmaf(w, hs.y, accy);
        }
    }

    float2 h0v = ((const float2*)g_h0)[(size_t)node * 32 + lane];
    float ox = 0.9f * accx + 0.1f * h0v.x;
    float oy = 0.9f * accy + 0.1f * h0v.y;
    if (out_sel == 3) {
        ((float2*)dout)[(size_t)node * 32 + lane] = make_float2(ox, oy);
    } else {
        __half2* ho = (__half2*)((out_sel == 1) ? g_fA : g_fB);
        ho[(size_t)node * 32 + lane] = __floats2half2_rn(ox, oy);
    }
}

// ---------------- launcher --------------------------------------------------------
extern "C" void kernel_launch(void* const* d_in, const int* in_sizes, int n_in,
                              void* d_out, int out_size) {
    const float* x  = (const float*)d_in[0];
    const void*  ei = d_in[1];
    const float* W1 = (const float*)d_in[2];
    const float* b1 = (const float*)d_in[3];
    const float* W2 = (const float*)d_in[4];
    const float* b2 = (const float*)d_in[5];

    int n = in_sizes[0] / IN_DIM;
    int E = in_sizes[1] / 2;

    cudaFuncSetAttribute(k_gemm1mma, cudaFuncAttributeMaxDynamicSharedMemorySize, 2 * G1_BUF);
    cudaFuncSetAttribute(k_gemm2mma, cudaFuncAttributeMaxDynamicSharedMemorySize, 2 * G2_BUF);

    // dtype detection + CSR build
    k_detect <<<1, 32>>>((const int*)ei);
    k_zero   <<<(n + 255) / 256, 256>>>(n);
    k_degree <<<(E + 255) / 256, 256>>>(ei, E);
    k_dinv   <<<(n + 255) / 256, 256>>>(n);
    k_scan   <<<1, 1024>>>(n);
    k_scatter<<<(E + 255) / 256, 256>>>(ei, E);

    // conversions
    k_convw<<<128, 256>>>(W1, W2);
    k_convx<<<2048, 256>>>(x, n * IN_DIM / 4);

    // MLP head on tensor cores (legacy mma.sync path)
    int mtiles = (n + 127) / 128;
    k_gemm1mma<<<mtiles, 256, 2 * G1_BUF>>>(b1, n);
    k_gemm2mma<<<mtiles, 256, 2 * G2_BUF>>>(b2, n);

    // K = 10 propagation steps, fp16 intermediates, final writes fp32 d_out
    int blocks = (n + 7) / 8;
    int in_sel = 0;
    for (int i = 0; i < 10; ++i) {
        int out_sel = (i == 9) ? 3 : ((i & 1) ? 2 : 1);
        k_prop<<<blocks, 256>>>(in_sel, out_sel, (float*)d_out, n);
        in_sel = out_sel;
    }
}